// round 9
// baseline (speedup 1.0000x reference)
#include <cuda_runtime.h>
#include <cuda_bf16.h>
#include <cstdint>

#define NTH   256                        // main kernels: 8 warps, m=32 per warp
#define PTH   512                        // prep kernels
#define ST    136                        // bf16 per weight-tile row (272 B stride)
#define TILEB (128 * ST * 2)             // 34816 B per 128x128 bf16 tile
#define EDGE_SMEM (6 * TILEB)            // W1a'(h,l) W1b(h,l) W2(h,l) = 208896
#define NODE_SMEM (4 * TILEB)            // U(h,l) V(h,l) = 139264
#define NODE_PAD 100096

// ---------------- device scratch (static, allowed) ----------------
__device__ __align__(16) float gVU[(size_t)NODE_PAD * 128];
__device__ __align__(16) float gVV[(size_t)NODE_PAD * 128];
__device__ __align__(16) float gW1a[128 * 128];
__device__ __align__(16) float gB1p[128];
__device__ __align__(16) char  gWimg[5][2][TILEB];  // 0:W1a' 1:W1b 2:W2 3:U_w 4:V_w

// ---------------- PTX helpers ----------------
__device__ __forceinline__ uint32_t smem_u32(const void* p) {
    uint32_t a;
    asm("{ .reg .u64 t; cvta.to.shared.u64 t, %1; cvt.u32.u64 %0, t; }" : "=r"(a) : "l"(p));
    return a;
}
#define LDSM4(r, addr)                                                              \
    asm volatile("ldmatrix.sync.aligned.m8n8.x4.shared.b16 {%0,%1,%2,%3}, [%4];"    \
                 : "=r"((r)[0]), "=r"((r)[1]), "=r"((r)[2]), "=r"((r)[3])           \
                 : "r"(addr))
__device__ __forceinline__ void mma_bf16(float* c, const uint32_t* a, uint32_t b0, uint32_t b1) {
    asm volatile("mma.sync.aligned.m16n8k16.row.col.f32.bf16.bf16.f32 "
                 "{%0,%1,%2,%3}, {%4,%5,%6,%7}, {%8,%9}, {%0,%1,%2,%3};"
                 : "+f"(c[0]), "+f"(c[1]), "+f"(c[2]), "+f"(c[3])
                 : "r"(a[0]), "r"(a[1]), "r"(a[2]), "r"(a[3]), "r"(b0), "r"(b1));
}
#define CP16(dst, src) \
    asm volatile("cp.async.ca.shared.global [%0], [%1], 16;" :: "r"(dst), "l"(src))
#define CP_COMMIT() asm volatile("cp.async.commit_group;" ::: "memory")
#define CP_WAIT()   asm volatile("cp.async.wait_group 0;" ::: "memory")

// ---------------- numeric helpers ----------------
__device__ __forceinline__ float bf16hi_rn(float a, uint32_t& hbits) {
    uint32_t u = __float_as_uint(a);
    uint32_t r = (u + 0x7FFFu + ((u >> 16) & 1u)) & 0xFFFF0000u;
    hbits = r;
    return __uint_as_float(r);
}
__device__ __forceinline__ uint32_t bf16x2_of(float lo, float hi) {
    uint32_t r;
    asm("cvt.rn.bf16x2.f32 %0, %1, %2;" : "=r"(r) : "f"(hi), "f"(lo));
    return r;
}
__device__ __forceinline__ void split2(float x, float y, uint32_t& h, uint32_t& l) {
    uint32_t rx, ry;
    float hx = bf16hi_rn(x, rx), hy = bf16hi_rn(y, ry);
    h = __byte_perm(rx, ry, 0x7632);
    l = bf16x2_of(x - hx, y - hy);
}
__device__ __forceinline__ float fast_tanh(float x) {
    float e = __expf(2.f * x);
    return 1.f - __fdividef(2.f, e + 1.f);
}
__device__ __forceinline__ float lk(float v) { return v > 0.f ? v : 0.01f * v; }

__device__ __forceinline__ void stage32(const float* __restrict__ src,
                                        char* Xh, char* Xl, uint32_t off) {
    #pragma unroll
    for (int i = 0; i < 8; ++i) {
        float4 t = reinterpret_cast<const float4*>(src)[i];
        uint32_t r0, r1, r2, r3;
        float h0 = bf16hi_rn(t.x, r0), h1 = bf16hi_rn(t.y, r1);
        float h2 = bf16hi_rn(t.z, r2), h3 = bf16hi_rn(t.w, r3);
        uint2 hh = make_uint2(__byte_perm(r0, r1, 0x7632), __byte_perm(r2, r3, 0x7632));
        uint2 ll = make_uint2(bf16x2_of(t.x - h0, t.y - h1), bf16x2_of(t.z - h2, t.w - h3));
        *reinterpret_cast<uint2*>(Xh + off + i * 8) = hh;
        *reinterpret_cast<uint2*>(Xl + off + i * 8) = ll;
    }
}

// ---------------- core MMA helper: one n-group (n=16), 3-term split ----------------
__device__ __forceinline__ void mma6(float* acc, const uint32_t* ah, const uint32_t* al,
                                     const uint32_t* bh, const uint32_t* bl) {
    mma_bf16(acc,     ah, bh[0], bh[1]);
    mma_bf16(acc,     ah, bl[0], bl[1]);
    mma_bf16(acc,     al, bh[0], bh[1]);
    mma_bf16(acc + 4, ah, bh[2], bh[3]);
    mma_bf16(acc + 4, ah, bl[2], bl[3]);
    mma_bf16(acc + 4, al, bh[2], bh[3]);
}

// ================= prep 1: W1a' = W1a @ P_w, b1' = b1 + W1a @ P_b =================
__global__ void __launch_bounds__(PTH, 1)
ecat_compose(const float* __restrict__ W1, const float* __restrict__ P_w,
             const float* __restrict__ P_b, const float* __restrict__ b1)
{
    int tid = threadIdx.x;
    int o = tid >> 2, jb = (tid & 3) * 32;
    float acc[32];
    #pragma unroll
    for (int j = 0; j < 32; ++j) acc[j] = 0.f;
    for (int i = 0; i < 128; ++i) {
        float w = W1[o * 256 + i];
        const float4* pr = reinterpret_cast<const float4*>(P_w + i * 128 + jb);
        #pragma unroll
        for (int j = 0; j < 8; ++j) {
            float4 p = pr[j];
            acc[4*j]   += w * p.x; acc[4*j+1] += w * p.y;
            acc[4*j+2] += w * p.z; acc[4*j+3] += w * p.w;
        }
    }
    #pragma unroll
    for (int j = 0; j < 8; ++j)
        reinterpret_cast<float4*>(gW1a + o * 128 + jb)[j] =
            make_float4(acc[4*j], acc[4*j+1], acc[4*j+2], acc[4*j+3]);
    if ((tid & 3) == 0) {
        float s = 0.f;
        for (int i = 0; i < 128; ++i) s += W1[o * 256 + i] * P_b[i];
        gB1p[o] = b1[o] + s;
    }
}

// ================= prep 2: weight tiles -> bf16 hi/lo smem images =================
__global__ void __launch_bounds__(PTH, 1)
ecat_convert(const float* __restrict__ W1, const float* __restrict__ W2,
             const float* __restrict__ U_w, const float* __restrict__ V_w)
{
    int b = blockIdx.x;
    int tid = threadIdx.x;
    int o = tid >> 2, qo = (tid & 3) * 32;
    const float* srcRow;
    if (b == 0)      srcRow = gW1a + o * 128 + qo;
    else if (b == 1) srcRow = W1 + o * 256 + 128 + qo;
    else if (b == 2) srcRow = W2 + o * 128 + qo;
    else if (b == 3) srcRow = U_w + (size_t)o * 128 + qo;
    else             srcRow = V_w + (size_t)o * 128 + qo;
    stage32(srcRow, (char*)gWimg[b][0], (char*)gWimg[b][1], (uint32_t)(o * ST + qo) * 2);
}

// ================= prep 3: VU = V@U_w^T, VV = V@V_w^T (persistent, m=32/warp) =================
__global__ void __launch_bounds__(NTH, 1)
ecat_node(const float* __restrict__ V, int n_nodes, int n_ntiles)
{
    extern __shared__ char sm[];
    uint32_t smb = smem_u32(sm);
    const char* gsrc = &gWimg[3][0][0];
    #pragma unroll
    for (int i = 0; i < 34; ++i) {                 // 34*256 = 8704 chunks exactly
        int idx = i * NTH + threadIdx.x;
        CP16(smb + idx * 16, gsrc + idx * 16);
    }
    CP_COMMIT(); CP_WAIT();
    __syncthreads();

    const int tid = threadIdx.x, lane = tid & 31, w = tid >> 5;
    const int r0 = lane >> 2, il = lane & 3, cb = il * 2;
    const uint32_t offB = (uint32_t)(((lane & 7) + (((lane >> 4) & 1) << 3)) * ST
                                     + (((lane >> 3) & 1) << 3)) * 2;

    for (int t = blockIdx.x; t < n_ntiles; t += gridDim.x) {
        int nb = t * 256 + w * 32 + r0;
        int nr[4];
        const float2* pa[4];
        #pragma unroll
        for (int q = 0; q < 4; ++q) {
            nr[q] = nb + q * 8;
            int nc = nr[q] < n_nodes ? nr[q] : 0;
            pa[q] = reinterpret_cast<const float2*>(V + (size_t)nc * 128);
        }

        #pragma unroll 1
        for (int pass = 0; pass < 2; ++pass) {
            uint32_t bH = smb + pass * 2 * TILEB, bL = bH + TILEB;
            float acc0[64], acc1[64];
            #pragma unroll
            for (int i = 0; i < 64; ++i) { acc0[i] = 0.f; acc1[i] = 0.f; }
            #pragma unroll 1
            for (int ks = 0; ks < 8; ++ks) {
                int i0 = il + 8 * ks, i1 = i0 + 4;
                uint32_t ah0[4], al0[4], ah1[4], al1[4];
                {
                    float2 a0 = pa[0][i0], b0 = pa[1][i0], c0 = pa[0][i1], d0 = pa[1][i1];
                    split2(a0.x, a0.y, ah0[0], al0[0]);
                    split2(b0.x, b0.y, ah0[1], al0[1]);
                    split2(c0.x, c0.y, ah0[2], al0[2]);
                    split2(d0.x, d0.y, ah0[3], al0[3]);
                    float2 a1 = pa[2][i0], b1v = pa[3][i0], c1 = pa[2][i1], d1 = pa[3][i1];
                    split2(a1.x, a1.y, ah1[0], al1[0]);
                    split2(b1v.x, b1v.y, ah1[1], al1[1]);
                    split2(c1.x, c1.y, ah1[2], al1[2]);
                    split2(d1.x, d1.y, ah1[3], al1[3]);
                }
                const uint32_t bHk = bH + offB + ks * 32, bLk = bL + offB + ks * 32;
                #pragma unroll
                for (int g = 0; g < 8; ++g) {
                    uint32_t go = (uint32_t)g * (16 * ST * 2);
                    uint32_t bh[4], bl[4];
                    LDSM4(bh, bHk + go);
                    LDSM4(bl, bLk + go);
                    mma6(acc0 + 8 * g, ah0, al0, bh, bl);
                    mma6(acc1 + 8 * g, ah1, al1, bh, bl);
                }
            }
            float* dstb = pass ? gVV : gVU;
            #pragma unroll
            for (int nf = 0; nf < 16; ++nf) {
                int c = nf * 8 + cb;
                if (nr[0] < n_nodes)
                    *reinterpret_cast<float2*>(dstb + (size_t)nr[0] * 128 + c) =
                        make_float2(acc0[nf*4], acc0[nf*4+1]);
                if (nr[1] < n_nodes)
                    *reinterpret_cast<float2*>(dstb + (size_t)nr[1] * 128 + c) =
                        make_float2(acc0[nf*4+2], acc0[nf*4+3]);
                if (nr[2] < n_nodes)
                    *reinterpret_cast<float2*>(dstb + (size_t)nr[2] * 128 + c) =
                        make_float2(acc1[nf*4], acc1[nf*4+1]);
                if (nr[3] < n_nodes)
                    *reinterpret_cast<float2*>(dstb + (size_t)nr[3] * 128 + c) =
                        make_float2(acc1[nf*4+2], acc1[nf*4+3]);
            }
        }
    }
}

// ================= main edge kernel: persistent, m=32/warp, merged A+B mainloop =================
__global__ void __launch_bounds__(NTH, 1)
ecat_edge(const float* __restrict__ E, const int* __restrict__ src,
          const int* __restrict__ dst, const float* __restrict__ b2,
          float* __restrict__ out, int n_tiles)
{
    extern __shared__ char sm[];
    uint32_t smb = smem_u32(sm);
    const char* gsrc = &gWimg[0][0][0];
    #pragma unroll
    for (int i = 0; i < 51; ++i) {                 // 51*256 = 13056 = 6*TILEB/16 exactly
        int idx = i * NTH + threadIdx.x;
        CP16(smb + idx * 16, gsrc + idx * 16);
    }
    CP_COMMIT(); CP_WAIT();
    __syncthreads();

    const int tid = threadIdx.x, lane = tid & 31, w = tid >> 5;
    const int r0 = lane >> 2, il = lane & 3, cb = il * 2;
    const uint32_t offB = (uint32_t)(((lane & 7) + (((lane >> 4) & 1) << 3)) * ST
                                     + (((lane >> 3) & 1) << 3)) * 2;
    const uint32_t uW1aH = smb,             uW1aL = smb + TILEB;
    const uint32_t uW1bH = smb + 2 * TILEB, uW1bL = smb + 3 * TILEB;
    const uint32_t uW2H  = smb + 4 * TILEB, uW2L  = smb + 5 * TILEB;

    for (int t = blockIdx.x; t < n_tiles; t += gridDim.x) {
        long eb = (long)t * 256 + w * 32 + r0;     // rows eb, eb+8, eb+16, eb+24
        const float2* pu[4];
        const float2* pv[4];
        #pragma unroll
        for (int q = 0; q < 4; ++q) {
            long er = eb + q * 8;
            pu[q] = reinterpret_cast<const float2*>(gVU + (size_t)__ldg(src + er) * 128);
            pv[q] = reinterpret_cast<const float2*>(gVV + (size_t)__ldg(dst + er) * 128);
        }
        const float2* pe = reinterpret_cast<const float2*>(E + eb * 128);  // +q*8*64 f2

        float acc0[64], acc1[64];
        #pragma unroll
        for (int i = 0; i < 64; ++i) { acc0[i] = 0.f; acc1[i] = 0.f; }

        // ---- merged GEMM A+B, both m-frags share every B fragment ----
        #pragma unroll 1
        for (int ks = 0; ks < 8; ++ks) {
            int i0 = il + 8 * ks, i1 = i0 + 4;
            uint32_t ath0[4], atl0[4], ath1[4], atl1[4];
            uint32_t aeh0[4], ael0[4], aeh1[4], ael1[4];
            {
                float2 u0 = pu[0][i0], u1 = pu[1][i0], u2 = pu[0][i1], u3 = pu[1][i1];
                float2 v0 = pv[0][i0], v1 = pv[1][i0], v2 = pv[0][i1], v3 = pv[1][i1];
                split2(fast_tanh(u0.x * v0.x), fast_tanh(u0.y * v0.y), ath0[0], atl0[0]);
                split2(fast_tanh(u1.x * v1.x), fast_tanh(u1.y * v1.y), ath0[1], atl0[1]);
                split2(fast_tanh(u2.x * v2.x), fast_tanh(u2.y * v2.y), ath0[2], atl0[2]);
                split2(fast_tanh(u3.x * v3.x), fast_tanh(u3.y * v3.y), ath0[3], atl0[3]);
            }
            {
                float2 u0 = pu[2][i0], u1 = pu[3][i0], u2 = pu[2][i1], u3 = pu[3][i1];
                float2 v0 = pv[2][i0], v1 = pv[3][i0], v2 = pv[2][i1], v3 = pv[3][i1];
                split2(fast_tanh(u0.x * v0.x), fast_tanh(u0.y * v0.y), ath1[0], atl1[0]);
                split2(fast_tanh(u1.x * v1.x), fast_tanh(u1.y * v1.y), ath1[1], atl1[1]);
                split2(fast_tanh(u2.x * v2.x), fast_tanh(u2.y * v2.y), ath1[2], atl1[2]);
                split2(fast_tanh(u3.x * v3.x), fast_tanh(u3.y * v3.y), ath1[3], atl1[3]);
            }
            {
                float2 e0 = pe[i0],            e1 = pe[512 + i0];
                float2 e2 = pe[i1],            e3 = pe[512 + i1];
                split2(lk(e0.x), lk(e0.y), aeh0[0], ael0[0]);
                split2(lk(e1.x), lk(e1.y), aeh0[1], ael0[1]);
                split2(lk(e2.x), lk(e2.y), aeh0[2], ael0[2]);
                split2(lk(e3.x), lk(e3.y), aeh0[3], ael0[3]);
                float2 f0 = pe[1024 + i0],     f1 = pe[1536 + i0];
                float2 f2 = pe[1024 + i1],     f3 = pe[1536 + i1];
                split2(lk(f0.x), lk(f0.y), aeh1[0], ael1[0]);
                split2(lk(f1.x), lk(f1.y), aeh1[1], ael1[1]);
                split2(lk(f2.x), lk(f2.y), aeh1[2], ael1[2]);
                split2(lk(f3.x), lk(f3.y), aeh1[3], ael1[3]);
            }
            const uint32_t bAH = uW1aH + offB + ks * 32, bAL = uW1aL + offB + ks * 32;
            const uint32_t bBH = uW1bH + offB + ks * 32, bBL = uW1bL + offB + ks * 32;
            #pragma unroll
            for (int g = 0; g < 8; ++g) {
                uint32_t go = (uint32_t)g * (16 * ST * 2);
                uint32_t bha[4], bla[4], bhb[4], blb[4];
                LDSM4(bha, bAH + go);
                LDSM4(bhb, bBH + go);
                LDSM4(bla, bAL + go);
                LDSM4(blb, bBL + go);
                mma6(acc0 + 8 * g, ath0, atl0, bha, bla);
                mma6(acc1 + 8 * g, ath1, atl1, bha, bla);
                mma6(acc0 + 8 * g, aeh0, ael0, bhb, blb);
                mma6(acc1 + 8 * g, aeh1, ael1, bhb, blb);
            }
        }

        // ---- y1 = relu(acc + b1'): repack C-frags directly into GEMM-C A-frags ----
        uint32_t yh0[8][4], yl0[8][4], yh1[8][4], yl1[8][4];
        #pragma unroll
        for (int ks = 0; ks < 8; ++ks) {
            #pragma unroll
            for (int p = 0; p < 2; ++p) {
                int nf = 2 * ks + p;
                float2 bb = __ldg(reinterpret_cast<const float2*>(gB1p + nf * 8 + cb));
                split2(fmaxf(acc0[nf*4+0] + bb.x, 0.f), fmaxf(acc0[nf*4+1] + bb.y, 0.f),
                       yh0[ks][2*p], yl0[ks][2*p]);
                split2(fmaxf(acc0[nf*4+2] + bb.x, 0.f), fmaxf(acc0[nf*4+3] + bb.y, 0.f),
                       yh0[ks][2*p+1], yl0[ks][2*p+1]);
                split2(fmaxf(acc1[nf*4+0] + bb.x, 0.f), fmaxf(acc1[nf*4+1] + bb.y, 0.f),
                       yh1[ks][2*p], yl1[ks][2*p]);
                split2(fmaxf(acc1[nf*4+2] + bb.x, 0.f), fmaxf(acc1[nf*4+3] + bb.y, 0.f),
                       yh1[ks][2*p+1], yl1[ks][2*p+1]);
            }
        }

        // ---- GEMM C: out = relu(y1 @ W2^T + b2), n in halves, both m-frags share B ----
        #pragma unroll 1
        for (int h = 0; h < 2; ++h) {
            float c0[32], c1[32];
            #pragma unroll
            for (int i = 0; i < 32; ++i) { c0[i] = 0.f; c1[i] = 0.f; }
            uint32_t hb = (uint32_t)h * (64 * ST * 2);
            #pragma unroll 1
            for (int ks = 0; ks < 8; ++ks) {
                const uint32_t bHk = uW2H + offB + hb + ks * 32;
                const uint32_t bLk = uW2L + offB + hb + ks * 32;
                #pragma unroll
                for (int g = 0; g < 4; ++g) {
                    uint32_t go = (uint32_t)g * (16 * ST * 2);
                    uint32_t bh[4], bl[4];
                    LDSM4(bh, bHk + go);
                    LDSM4(bl, bLk + go);
                    mma6(c0 + 8 * g, yh0[ks], yl0[ks], bh, bl);
                    mma6(c1 + 8 * g, yh1[ks], yl1[ks], bh, bl);
                }
            }
            #pragma unroll
            for (int nf = 0; nf < 8; ++nf) {
                int c = h * 64 + nf * 8 + cb;
                float2 bb = __ldg(reinterpret_cast<const float2*>(b2 + c));
                float* o0 = out + (eb)      * 128 + c;
                float* o1 = out + (eb + 8)  * 128 + c;
                float* o2 = out + (eb + 16) * 128 + c;
                float* o3 = out + (eb + 24) * 128 + c;
                *reinterpret_cast<float2*>(o0) =
                    make_float2(fmaxf(c0[nf*4+0] + bb.x, 0.f), fmaxf(c0[nf*4+1] + bb.y, 0.f));
                *reinterpret_cast<float2*>(o1) =
                    make_float2(fmaxf(c0[nf*4+2] + bb.x, 0.f), fmaxf(c0[nf*4+3] + bb.y, 0.f));
                *reinterpret_cast<float2*>(o2) =
                    make_float2(fmaxf(c1[nf*4+0] + bb.x, 0.f), fmaxf(c1[nf*4+1] + bb.y, 0.f));
                *reinterpret_cast<float2*>(o3) =
                    make_float2(fmaxf(c1[nf*4+2] + bb.x, 0.f), fmaxf(c1[nf*4+3] + bb.y, 0.f));
            }
        }
    }
}

// ================= host =================
extern "C" void kernel_launch(void* const* d_in, const int* in_sizes, int n_in,
                              void* d_out, int out_size)
{
    const float* V   = (const float*)d_in[0];
    const float* E   = (const float*)d_in[1];
    const int*   src = (const int*)d_in[2];
    const int*   dst = (const int*)d_in[3];
    const float* U_w = (const float*)d_in[4];
    const float* V_w = (const float*)d_in[5];
    const float* P_w = (const float*)d_in[6];
    const float* P_b = (const float*)d_in[7];
    const float* W1  = (const float*)d_in[8];
    const float* b1  = (const float*)d_in[9];
    const float* W2  = (const float*)d_in[10];
    const float* b2  = (const float*)d_in[11];
    float* out = (float*)d_out;

    int n_nodes = in_sizes[0] / 128;
    int n_edges = in_sizes[2];
    int n_tiles = n_edges / 256;                 // 2500
    int n_ntiles = (n_nodes + 255) / 256;        // 391

    static int sms = 0;
    if (!sms) {
        cudaDeviceGetAttribute(&sms, cudaDevAttrMultiProcessorCount, 0);
        cudaFuncSetAttribute(ecat_node, cudaFuncAttributeMaxDynamicSharedMemorySize, NODE_SMEM);
        cudaFuncSetAttribute(ecat_edge, cudaFuncAttributeMaxDynamicSharedMemorySize, EDGE_SMEM);
    }

    ecat_compose<<<1, PTH>>>(W1, P_w, P_b, b1);
    ecat_convert<<<5, PTH>>>(W1, W2, U_w, V_w);
    ecat_node<<<sms, NTH, NODE_SMEM>>>(V, n_nodes, n_ntiles);
    ecat_edge<<<sms, NTH, EDGE_SMEM>>>(E, src, dst, b2, out, n_tiles);
}